// round 10
// baseline (speedup 1.0000x reference)
#include <cuda_runtime.h>
#include <cuda_bf16.h>
#include <math.h>
#include <stdint.h>

// ---------------------------------------------------------------------------
// Problem constants
// ---------------------------------------------------------------------------
#define Nn 16            // B*T
#define Cc 512
#define Ss 1024          // H*W
#define NHEADS 8
#define HD 64
#define D3 1536          // 3*C

typedef __nv_bfloat16 bf16;

// ---------------------------------------------------------------------------
// Scratch (device globals; no cudaMalloc allowed)
// ---------------------------------------------------------------------------
__device__ bf16 g_hn   [Nn * Ss * Cc];           // [n][s][c]
__device__ bf16 g_q    [Nn * NHEADS * Ss * HD];  // [nh][s][e]
__device__ bf16 g_k    [Nn * NHEADS * Ss * HD];  // [nh][s][e]
__device__ bf16 g_v    [Nn * NHEADS * HD * Ss];  // [nh][e][s] (transposed)
__device__ bf16 g_att  [Nn * Ss * Cc];           // [n][s][c]
__device__ bf16 g_wqkvT[D3 * Cc];                // [d][c]
__device__ bf16 g_woutT[Cc * Cc];                // [c2][c]

// ---------------------------------------------------------------------------
// Helpers
// ---------------------------------------------------------------------------
__device__ __forceinline__ uint32_t smem_u32(const void* p) {
    uint32_t a;
    asm("{ .reg .u64 t; cvta.to.shared.u64 t, %1; cvt.u32.u64 %0, t; }"
        : "=r"(a) : "l"(p));
    return a;
}

// pack two fp32 -> bf16x2 (lo = first arg)
__device__ __forceinline__ uint32_t packbf(float lo, float hi) {
    uint32_t r;
    asm("cvt.rn.bf16x2.f32 %0, %1, %2;" : "=r"(r) : "f"(hi), "f"(lo));
    return r;
}

// m16n8k16 bf16 mma, D = A*B + D (in place), fp32 accumulate
__device__ __forceinline__ void mma16(float* d, const uint32_t* a, const uint32_t* b) {
    asm volatile(
        "mma.sync.aligned.m16n8k16.row.col.f32.bf16.bf16.f32 "
        "{%0,%1,%2,%3}, {%4,%5,%6,%7}, {%8,%9}, {%0,%1,%2,%3};"
        : "+f"(d[0]), "+f"(d[1]), "+f"(d[2]), "+f"(d[3])
        : "r"(a[0]), "r"(a[1]), "r"(a[2]), "r"(a[3]), "r"(b[0]), "r"(b[1]));
}

__device__ __forceinline__ void cp16(uint32_t dst, const void* src) {
    asm volatile("cp.async.cg.shared.global [%0], [%1], 16;" :: "r"(dst), "l"(src));
}
#define CP_COMMIT() asm volatile("cp.async.commit_group;" ::: "memory")
#define CP_WAIT1()  asm volatile("cp.async.wait_group 1;" ::: "memory")

// ---------------------------------------------------------------------------
// Kernel 0: weight transpose + bf16 rounding   in [512][Ccols] -> out [Ccols][512]
// ---------------------------------------------------------------------------
__global__ void __launch_bounds__(256) trans_kernel(const float* __restrict__ in,
                                                    int Ccols, int which)
{
    bf16* out = which ? g_woutT : g_wqkvT;
    __shared__ float t[32][33];
    int c0 = blockIdx.x * 32, r0 = blockIdx.y * 32;
    int tx = threadIdx.x, ty = threadIdx.y;
#pragma unroll
    for (int i = 0; i < 32; i += 8)
        t[ty + i][tx] = in[(size_t)(r0 + ty + i) * Ccols + c0 + tx];
    __syncthreads();
#pragma unroll
    for (int i = 0; i < 32; i += 8)
        out[(size_t)(c0 + ty + i) * 512 + r0 + tx] = __float2bfloat16_rn(t[tx][ty + i]);
}

// ---------------------------------------------------------------------------
// Kernel 1: GroupNorm (32 groups, eps=1e-6) -> g_hn [n][s][c] (bf16)
// ---------------------------------------------------------------------------
__global__ void __launch_bounds__(256) gn_kernel(const float* __restrict__ x,
                                                 const float* __restrict__ sc,
                                                 const float* __restrict__ bi)
{
    extern __shared__ float smt[];   // [1024][17]
    int n = blockIdx.x >> 5;
    int g = blockIdx.x & 31;
    const float* px = x + (size_t)(n * Cc + g * 16) * Ss;
    bf16* ph = g_hn + (size_t)n * Ss * Cc + g * 16;
    int tid = threadIdx.x;
    const int M = 16 * Ss;

    float s = 0.f, ss = 0.f;
    for (int i = tid * 4; i < M; i += 1024) {
        float4 v = *(const float4*)&px[i];
        s  += v.x + v.y + v.z + v.w;
        ss += v.x*v.x + v.y*v.y + v.z*v.z + v.w*v.w;
    }
#pragma unroll
    for (int o = 16; o; o >>= 1) {
        s  += __shfl_xor_sync(0xffffffffu, s,  o);
        ss += __shfl_xor_sync(0xffffffffu, ss, o);
    }
    __shared__ float r0[8], r1[8];
    __shared__ float s_mean, s_inv;
    if ((tid & 31) == 0) { r0[tid >> 5] = s; r1[tid >> 5] = ss; }
    __syncthreads();
    if (tid == 0) {
        float a = 0.f, b2 = 0.f;
#pragma unroll
        for (int i = 0; i < 8; i++) { a += r0[i]; b2 += r1[i]; }
        float mean = a / (float)M;
        float var  = b2 / (float)M - mean * mean;
        s_mean = mean;
        s_inv  = rsqrtf(var + 1e-6f);
    }
    __syncthreads();
    float mean = s_mean, inv = s_inv;

    for (int i = tid * 4; i < M; i += 1024) {
        int c  = i >> 10;
        int sp = i & 1023;
        float scv = sc[g * 16 + c] * inv;
        float biv = bi[g * 16 + c] - mean * scv;
        float4 v = *(const float4*)&px[i];
        smt[(sp + 0) * 17 + c] = v.x * scv + biv;
        smt[(sp + 1) * 17 + c] = v.y * scv + biv;
        smt[(sp + 2) * 17 + c] = v.z * scv + biv;
        smt[(sp + 3) * 17 + c] = v.w * scv + biv;
    }
    __syncthreads();

    // write 16-bf16 rows (32 B = 2 x 16B stores)
#pragma unroll
    for (int j = 0; j < 4; j++) {
        int sp = tid * 4 + j;
        const float* row = &smt[sp * 17];
        uint32_t pk[8];
#pragma unroll
        for (int q = 0; q < 8; q++) pk[q] = packbf(row[2*q], row[2*q+1]);
        uint4* dst = (uint4*)(ph + (size_t)sp * Cc);
        dst[0] = make_uint4(pk[0], pk[1], pk[2], pk[3]);
        dst[1] = make_uint4(pk[4], pk[5], pk[6], pk[7]);
    }
}

// ---------------------------------------------------------------------------
// Kernel 2: bf16 m16n8k16 GEMM, tile 128x128, K=512, BK=32, 3-stage cp.async.
// 256 threads = 8 warps as 4(M) x 2(N); warp tile 32x64.
// SMEM: bf16, row stride 40 (80 B) => conflict-free fragment loads.
// Stage = (128*40)*2 matrices * 2B = 20480 B; 3 stages = 61440 B.
// ---------------------------------------------------------------------------
__device__ __forceinline__ void gemm_load(uint32_t sbase, int soff,
                                          const bf16* __restrict__ Ag,
                                          const bf16* __restrict__ Bg,
                                          int koff, int tid)
{
#pragma unroll
    for (int i = 0; i < 2; i++) {
        int f = tid + i * 256;
        int row = f >> 2, c = f & 3;          // 4 x 16B chunks per 32-bf16 row
        cp16(sbase + (uint32_t)(soff + row * 80 + c * 16),
             Ag + (size_t)row * Cc + koff + c * 8);
        cp16(sbase + (uint32_t)(soff + 10240 + row * 80 + c * 16),
             Bg + (size_t)row * Cc + koff + c * 8);
    }
}

__global__ void __launch_bounds__(256, 2) gemm_mma(const float* __restrict__ bias,
                                                   const float* __restrict__ xres,
                                                   float* __restrict__ out,
                                                   int mode)
{
    extern __shared__ char smc[];
    uint32_t sbase = smem_u32(smc);
    int tid = threadIdx.x, lane = tid & 31, wid = tid >> 5;
    int g = lane >> 2, tg = lane & 3;
    int n = blockIdx.z, s0 = blockIdx.x * 128, d0 = blockIdx.y * 128;
    int wm = wid & 3, wn = wid >> 2;

    const bf16* Ag = (mode ? g_att : g_hn) + ((size_t)n * Ss + s0) * Cc;
    const bf16* Bg = (mode ? g_woutT : g_wqkvT) + (size_t)d0 * Cc;

    float C[2][8][4] = {};

    gemm_load(sbase, 0, Ag, Bg, 0, tid);
    CP_COMMIT();
    gemm_load(sbase, 20480, Ag, Bg, 32, tid);
    CP_COMMIT();

    for (int kc = 0; kc < 16; kc++) {
        CP_WAIT1();
        __syncthreads();
        int b = kc % 3;
        if (kc + 2 < 16)
            gemm_load(sbase, ((kc + 2) % 3) * 20480, Ag, Bg, (kc + 2) * 32, tid);
        CP_COMMIT();

        const bf16* As = (const bf16*)(smc + b * 20480);
        const bf16* Bs = (const bf16*)(smc + b * 20480 + 10240);
#pragma unroll
        for (int ks = 0; ks < 2; ks++) {       // two k16 steps per BK=32
            int k0 = ks * 16;
            uint32_t a[2][4], bb[8][2];
#pragma unroll
            for (int tm = 0; tm < 2; tm++) {
                int r = wm * 32 + tm * 16 + g;
                a[tm][0] = *(const uint32_t*)&As[r * 40 + k0 + 2 * tg];
                a[tm][1] = *(const uint32_t*)&As[(r + 8) * 40 + k0 + 2 * tg];
                a[tm][2] = *(const uint32_t*)&As[r * 40 + k0 + 2 * tg + 8];
                a[tm][3] = *(const uint32_t*)&As[(r + 8) * 40 + k0 + 2 * tg + 8];
            }
#pragma unroll
            for (int tn = 0; tn < 8; tn++) {
                int c = wn * 64 + tn * 8 + g;
                bb[tn][0] = *(const uint32_t*)&Bs[c * 40 + k0 + 2 * tg];
                bb[tn][1] = *(const uint32_t*)&Bs[c * 40 + k0 + 2 * tg + 8];
            }
#pragma unroll
            for (int tm = 0; tm < 2; tm++)
#pragma unroll
                for (int tn = 0; tn < 8; tn++)
                    mma16(C[tm][tn], a[tm], bb[tn]);
        }
    }

    // epilogue
#pragma unroll
    for (int tm = 0; tm < 2; tm++) {
#pragma unroll
        for (int hh = 0; hh < 2; hh++) {
            int m = s0 + wm * 32 + tm * 16 + g + hh * 8;
#pragma unroll
            for (int tn = 0; tn < 8; tn++) {
                int d = d0 + wn * 64 + tn * 8 + 2 * tg;
                float v0 = C[tm][tn][hh * 2 + 0] + __ldg(&bias[d]);
                float v1 = C[tm][tn][hh * 2 + 1] + __ldg(&bias[d + 1]);
                if (mode == 0) {
                    int head = d / 192, t = d % 192;
                    int part = t >> 6, e = t & 63;
                    size_t nh = (size_t)(n * 8 + head);
                    if (part == 0) {
                        *(uint32_t*)&g_q[(nh * Ss + m) * HD + e] = packbf(v0, v1);
                    } else if (part == 1) {
                        *(uint32_t*)&g_k[(nh * Ss + m) * HD + e] = packbf(v0, v1);
                    } else {
                        g_v[(nh * HD + e) * Ss + m]     = __float2bfloat16_rn(v0);
                        g_v[(nh * HD + e + 1) * Ss + m] = __float2bfloat16_rn(v1);
                    }
                } else {
                    size_t gi = ((size_t)n * Cc + d) * Ss + m;
                    out[gi]      = v0 + xres[gi];
                    out[gi + Ss] = v1 + xres[gi + Ss];
                }
            }
        }
    }
}

// ---------------------------------------------------------------------------
// Kernel 3: flash attention, bf16 m16n8k16, double-buffered cp.async K/V.
// P stays in registers: bf16 C-frag layout == A-frag layout (no shuffles).
// SMEM bytes: KV stage b: K at b*18432, V at +9216; Q at 36864. Total 55296.
// Row stride 72 bf16 (144 B) => conflict-free + 16B-aligned cp.async.
// ---------------------------------------------------------------------------
#define ATT_SMEM 55296

__device__ __forceinline__ void attn_load_kv(uint32_t sbase, int b,
                                             const bf16* __restrict__ K,
                                             const bf16* __restrict__ V,
                                             int kt, int tid)
{
#pragma unroll
    for (int i = 0; i < 2; i++) {
        int f = tid + i * 256;
        int r = f >> 3, c = f & 7;            // 8 x 16B chunks per 64-bf16 row
        cp16(sbase + (uint32_t)(b * 18432 + r * 144 + c * 16),
             K + (size_t)(kt * 64 + r) * HD + c * 8);
        cp16(sbase + (uint32_t)(b * 18432 + 9216 + r * 144 + c * 16),
             V + (size_t)r * Ss + kt * 64 + c * 8);
    }
}

__global__ void __launch_bounds__(256, 2) attn_mma()
{
    extern __shared__ char smc[];
    uint32_t sbase = smem_u32(smc);
    const bf16* Qs = (const bf16*)(smc + 36864);

    int tid = threadIdx.x, lane = tid & 31, w = tid >> 5;
    int g = lane >> 2, tg = lane & 3;
    int nh = blockIdx.y, q0 = blockIdx.x * 128;
    const bf16* Q = g_q + (size_t)nh * Ss * HD;
    const bf16* K = g_k + (size_t)nh * Ss * HD;
    const bf16* V = g_v + (size_t)nh * HD * Ss;

    // prologue: Q + KV(0) -> group 0; KV(1) -> group 1
#pragma unroll
    for (int i = 0; i < 4; i++) {
        int f = tid + i * 256;
        int row = f >> 3, c = f & 7;
        cp16(sbase + (uint32_t)(36864 + row * 144 + c * 16),
             Q + (size_t)(q0 + row) * HD + c * 8);
    }
    attn_load_kv(sbase, 0, K, V, 0, tid);
    CP_COMMIT();
    attn_load_kv(sbase, 1, K, V, 1, tid);
    CP_COMMIT();

    float O[8][4] = {};
    float m0 = -1e30f, m1 = -1e30f, l0 = 0.f, l1 = 0.f;
    int qb = w * 16;

    for (int kt = 0; kt < 16; kt++) {
        CP_WAIT1();
        __syncthreads();
        int b = kt & 1;
        const bf16* Ks = (const bf16*)(smc + b * 18432);
        const bf16* Vs = (const bf16*)(smc + b * 18432 + 9216);

        // S = Q @ K^T  (warp: 16 q rows x 64 keys), k-dim = e: 4 k16 steps
        float S[8][4] = {};
#pragma unroll
        for (int ks = 0; ks < 4; ks++) {
            int k0 = ks * 16;
            uint32_t a[4];
            a[0] = *(const uint32_t*)&Qs[(qb + g) * 72 + k0 + 2 * tg];
            a[1] = *(const uint32_t*)&Qs[(qb + g + 8) * 72 + k0 + 2 * tg];
            a[2] = *(const uint32_t*)&Qs[(qb + g) * 72 + k0 + 2 * tg + 8];
            a[3] = *(const uint32_t*)&Qs[(qb + g + 8) * 72 + k0 + 2 * tg + 8];
#pragma unroll
            for (int tn = 0; tn < 8; tn++) {
                uint32_t bfr[2];
                bfr[0] = *(const uint32_t*)&Ks[(tn * 8 + g) * 72 + k0 + 2 * tg];
                bfr[1] = *(const uint32_t*)&Ks[(tn * 8 + g) * 72 + k0 + 2 * tg + 8];
                mma16(S[tn], a, bfr);
            }
        }

        // scale + online softmax
        float mx0 = -1e30f, mx1 = -1e30f;
#pragma unroll
        for (int tn = 0; tn < 8; tn++) {
            S[tn][0] *= 0.125f; S[tn][1] *= 0.125f;
            S[tn][2] *= 0.125f; S[tn][3] *= 0.125f;
            mx0 = fmaxf(mx0, fmaxf(S[tn][0], S[tn][1]));
            mx1 = fmaxf(mx1, fmaxf(S[tn][2], S[tn][3]));
        }
        mx0 = fmaxf(mx0, __shfl_xor_sync(0xffffffffu, mx0, 1));
        mx0 = fmaxf(mx0, __shfl_xor_sync(0xffffffffu, mx0, 2));
        mx1 = fmaxf(mx1, __shfl_xor_sync(0xffffffffu, mx1, 1));
        mx1 = fmaxf(mx1, __shfl_xor_sync(0xffffffffu, mx1, 2));
        float mn0 = fmaxf(m0, mx0), mn1 = fmaxf(m1, mx1);
        float cr0 = __expf(m0 - mn0), cr1 = __expf(m1 - mn1);
        float rs0 = 0.f, rs1 = 0.f;
#pragma unroll
        for (int tn = 0; tn < 8; tn++) {
            S[tn][0] = __expf(S[tn][0] - mn0);
            S[tn][1] = __expf(S[tn][1] - mn0);
            S[tn][2] = __expf(S[tn][2] - mn1);
            S[tn][3] = __expf(S[tn][3] - mn1);
            rs0 += S[tn][0] + S[tn][1];
            rs1 += S[tn][2] + S[tn][3];
        }
        rs0 += __shfl_xor_sync(0xffffffffu, rs0, 1);
        rs0 += __shfl_xor_sync(0xffffffffu, rs0, 2);
        rs1 += __shfl_xor_sync(0xffffffffu, rs1, 1);
        rs1 += __shfl_xor_sync(0xffffffffu, rs1, 2);
        l0 = l0 * cr0 + rs0;  l1 = l1 * cr1 + rs1;
        m0 = mn0;  m1 = mn1;

        // pack P to bf16 (C-frag layout == A-frag layout: no shuffles!)
        uint32_t Pp[8][2];
#pragma unroll
        for (int tn = 0; tn < 8; tn++) {
            O[tn][0] *= cr0; O[tn][1] *= cr0;
            O[tn][2] *= cr1; O[tn][3] *= cr1;
            Pp[tn][0] = packbf(S[tn][0], S[tn][1]);   // row g,   cols 2tg,2tg+1
            Pp[tn][1] = packbf(S[tn][2], S[tn][3]);   // row g+8, cols 2tg,2tg+1
        }

        // O += P @ V : 4 k16 steps over j
#pragma unroll
        for (int ks = 0; ks < 4; ks++) {
            int k0 = ks * 16;
            uint32_t a[4];
            a[0] = Pp[2 * ks][0];        // row g,   j 16ks+2tg,+1
            a[1] = Pp[2 * ks][1];        // row g+8
            a[2] = Pp[2 * ks + 1][0];    // row g,   j 16ks+2tg+8,+9
            a[3] = Pp[2 * ks + 1][1];
#pragma unroll
            for (int tn = 0; tn < 8; tn++) {
                uint32_t bfr[2];
                bfr[0] = *(const uint32_t*)&Vs[(tn * 8 + g) * 72 + k0 + 2 * tg];
                bfr[1] = *(const uint32_t*)&Vs[(tn * 8 + g) * 72 + k0 + 2 * tg + 8];
                mma16(O[tn], a, bfr);
            }
        }

        __syncthreads();
        if (kt + 2 < 16)
            attn_load_kv(sbase, b, K, V, kt + 2, tid);
        CP_COMMIT();
    }

    // epilogue -> g_att[n][s][head*64 + e] (bf16 pairs)
    int n = nh >> 3, head = nh & 7;
    float inv0 = 1.f / l0, inv1 = 1.f / l1;
    int srow0 = q0 + qb + g, srow1 = srow0 + 8;
    bf16* dst = g_att + (size_t)n * Ss * Cc + head * 64;
#pragma unroll
    for (int tn = 0; tn < 8; tn++) {
        int c = tn * 8 + 2 * tg;
        *(uint32_t*)&dst[(size_t)srow0 * Cc + c] = packbf(O[tn][0] * inv0, O[tn][1] * inv0);
        *(uint32_t*)&dst[(size_t)srow1 * Cc + c] = packbf(O[tn][2] * inv1, O[tn][3] * inv1);
    }
}

// ---------------------------------------------------------------------------
extern "C" void kernel_launch(void* const* d_in, const int* in_sizes, int n_in,
                              void* d_out, int out_size)
{
    const float* x    = (const float*)d_in[0];
    const float* gsc  = (const float*)d_in[1];
    const float* gbi  = (const float*)d_in[2];
    const float* wqkv = (const float*)d_in[3];
    const float* bqkv = (const float*)d_in[4];
    const float* wout = (const float*)d_in[5];
    const float* bout = (const float*)d_in[6];
    float* out = (float*)d_out;

    trans_kernel<<<dim3(D3 / 32, Cc / 32), dim3(32, 8)>>>(wqkv, D3, 0);
    trans_kernel<<<dim3(Cc / 32, Cc / 32), dim3(32, 8)>>>(wout, Cc, 1);

    cudaFuncSetAttribute(gn_kernel, cudaFuncAttributeMaxDynamicSharedMemorySize, 69632);
    gn_kernel<<<Nn * 32, 256, 69632>>>(x, gsc, gbi);

    const int gemm_smem = 61440;   // 3 stages x 20480 B
    cudaFuncSetAttribute(gemm_mma, cudaFuncAttributeMaxDynamicSharedMemorySize, gemm_smem);
    gemm_mma<<<dim3(Ss / 128, D3 / 128, Nn), 256, gemm_smem>>>(bqkv, nullptr, nullptr, 0);

    cudaFuncSetAttribute(attn_mma, cudaFuncAttributeMaxDynamicSharedMemorySize, ATT_SMEM);
    attn_mma<<<dim3(Ss / 128, Nn * NHEADS), 256, ATT_SMEM>>>();

    gemm_mma<<<dim3(Ss / 128, Cc / 128, Nn), 256, gemm_smem>>>(bout, x, out, 1);
}